// round 14
// baseline (speedup 1.0000x reference)
#include <cuda_runtime.h>
#include <math.h>

// ============================================================================
// ProgramTransformer sampling — JAX threefry PARTITIONABLE mode.
// One warp per batch row. Hoisted/packed RNG (4 warp threefrys + conditional
// t2-hi). redux.sync reductions; integer-redux z-sum; fast-math softmax path
// (cannot flip actions); gumbel logf full precision (decides actions).
// ============================================================================

struct Keys6 { unsigned k[12]; };

// ---------------- threefry2x32 (JAX schedule, 20 rounds) ----------------
__device__ __forceinline__ void tf2x32(unsigned k0, unsigned k1,
                                       unsigned x0, unsigned x1,
                                       unsigned &o0, unsigned &o1)
{
    unsigned ks2 = k0 ^ k1 ^ 0x1BD11BDAu;
    x0 += k0; x1 += k1;
#define TFR(r) { x0 += x1; x1 = __funnelshift_l(x1, x1, (r)); x1 ^= x0; }
    TFR(13) TFR(15) TFR(26) TFR(6)
    x0 += k1;  x1 += ks2 + 1u;
    TFR(17) TFR(29) TFR(16) TFR(24)
    x0 += ks2; x1 += k0 + 2u;
    TFR(13) TFR(15) TFR(26) TFR(6)
    x0 += k0;  x1 += k1 + 3u;
    TFR(17) TFR(29) TFR(16) TFR(24)
    x0 += k1;  x1 += ks2 + 4u;
    TFR(13) TFR(15) TFR(26) TFR(6)
    x0 += ks2; x1 += k0 + 5u;
#undef TFR
    o0 = x0; o1 = x1;
}

// partitionable 32-bit random bits for flat element idx
__device__ __forceinline__ unsigned tf_bits(unsigned k0, unsigned k1, unsigned idx)
{
    unsigned o0, o1;
    tf2x32(k0, k1, 0u, idx, o0, o1);
    return o0 ^ o1;
}

// jax uniform(minval=tiny,maxval=1) -> gumbel (full-precision: decides argmax)
__device__ __forceinline__ float jax_gumbel(unsigned bits)
{
    const float tiny = 1.17549435082228751e-38f;
    float f = __uint_as_float((bits >> 9) | 0x3f800000u) - 1.0f;
    float u = fmaxf(tiny, f + tiny);
    return -logf(-logf(u));
}

// float -> order-preserving unsigned (and back)
__device__ __forceinline__ unsigned f2o(float f)
{
    unsigned b = __float_as_uint(f);
    return (b & 0x80000000u) ? ~b : (b | 0x80000000u);
}
__device__ __forceinline__ float o2f(unsigned u)
{
    return __uint_as_float((u & 0x80000000u) ? (u ^ 0x80000000u) : ~u);
}

struct SR1 { int a; float lp, lpm; };

// integer-redux sum of z terms scaled by 2^24 (terms in [0,1])
__device__ __forceinline__ float zsum_redux(float zterm)
{
    const unsigned FULL = 0xFFFFFFFFu;
    int zi = __float2int_rn(zterm * 16777216.0f);
    int zs = __reduce_add_sync(FULL, zi);
    return (float)zs * 5.9604644775390625e-8f;   // 2^-24
}

// ---------------- single-slot sampler (only cols 0..31 live) ----------------
__device__ __forceinline__ void sampleLo(float v, float s, float m, int lane, SR1 &r)
{
    const unsigned FULL = 0xFFFFFFFFu;
    unsigned u = f2o(v);
    unsigned umax = __reduce_max_sync(FULL, u);
    int a = __reduce_min_sync(FULL, (u == umax) ? lane : 127);
    float mx = o2f(__reduce_max_sync(FULL, f2o(s)));
    int cnt = __popc(__ballot_sync(FULL, m == 0.0f));
    float z = zsum_redux(__expf(s - mx));   // s=-inf -> 0
    float sact = __shfl_sync(FULL, s, a);
    r.a = a;
    r.lp = sact - mx - __logf(z);
    r.lpm = (cnt > 1) ? 1.0f : 0.0f;
}

// ---------------- two-slot sampler (cols lane and lane+32) ----------------
__device__ __forceinline__ void sampleHiLo(float va, float vb,
                                           float sa, float sb,
                                           float ma, float mb, int lane, SR1 &r)
{
    const unsigned FULL = 0xFFFFFFFFu;
    float bv = va; int bi = lane;
    if (vb > bv) { bv = vb; bi = lane + 32; }   // tie -> keep smaller col
    unsigned u = f2o(bv);
    unsigned umax = __reduce_max_sync(FULL, u);
    int a = __reduce_min_sync(FULL, (u == umax) ? bi : 127);
    float mx = o2f(__reduce_max_sync(FULL, f2o(fmaxf(sa, sb))));
    int cnt = __popc(__ballot_sync(FULL, ma == 0.0f)) +
              __popc(__ballot_sync(FULL, mb == 0.0f));
    float z = zsum_redux(__expf(sa - mx) + __expf(sb - mx));  // terms sum <= 2
    float ps = (a >= 32) ? sb : sa;
    float sact = __shfl_sync(FULL, ps, a & 31);
    r.a = a;
    r.lp = sact - mx - __logf(z);
    r.lpm = (cnt > 1) ? 1.0f : 0.0f;
}

// ============================================================================
__global__ void __launch_bounds__(256)
pt_kernel(int B,
          const float* __restrict__ order_mask,
          const int*   __restrict__ budgets,
          const float* __restrict__ tile_masks,
          const float* __restrict__ remain,
          const int*   __restrict__ tile2_max,
          const float* __restrict__ max_temporal,
          const int*   __restrict__ sp_max_p,
          const int*   __restrict__ sp_min_p,
          const float* __restrict__ order_logit,
          const float* __restrict__ tile_logits,
          const float* __restrict__ sp_logit,
          const int*   __restrict__ d_loop,
          int li_const,
          float* __restrict__ out,
          Keys6 keys)
{
    const unsigned FULL = 0xFFFFFFFFu;
    const float NEGINF = __int_as_float(0xff800000);
    int gt = blockIdx.x * blockDim.x + threadIdx.x;
    int b = gt >> 5;
    if (b >= B) return;
    int lane = gt & 31;
    int li = d_loop ? d_loop[0] : li_const;

    int ca = lane, cb = lane + 32;
    unsigned b64 = (unsigned)(b * 64);
    int base_tm = b * 1792 + li * 256;       // tile_masks (B,7,4,64)

    // ======== hoisted random bits (4 warp-wide threefry+gumbel) ========
    float g_ord  = jax_gumbel(tf_bits(keys.k[0], keys.k[1],
                                      (unsigned)(b * 7) + (unsigned)lane));
    float g_sp   = jax_gumbel(tf_bits(keys.k[2], keys.k[3], b64 + (unsigned)lane));
    float g_t2a  = jax_gumbel(tf_bits(keys.k[4], keys.k[5], b64 + (unsigned)lane));
    // packed p1/p2/p3 (keys 3/4/5): p1 cols0-12 lanes0-12, p2 cols0-8
    // lanes13-21, p3 cols0-7 lanes22-29; lanes 30-31 duplicate p3 col0.
    unsigned pk0, pk1, poff;
    if (lane < 13)      { pk0 = keys.k[6];  pk1 = keys.k[7];  poff = (unsigned)lane; }
    else if (lane < 22) { pk0 = keys.k[8];  pk1 = keys.k[9];  poff = (unsigned)(lane - 13); }
    else                { pk0 = keys.k[10]; pk1 = keys.k[11]; poff = (lane < 30) ? (unsigned)(lane - 22) : 0u; }
    float g_pack = jax_gumbel(tf_bits(pk0, pk1, b64 + poff));

    // ---------------- order sampling (C=7, keys[0]) ----------------
    float om = NEGINF, os = NEGINF;
    if (lane < 7) {
        om = order_mask[b * 7 + lane];
        os = order_logit[b * 7 + lane] + om;
    }
    SR1 ro;
    sampleLo(lane < 7 ? (g_ord + os) : NEGINF, os, om, lane, ro);

    // ---------------- sp sampling (upper half always masked) ----------------
    float tba = tile_masks[base_tm + ca];
    int sx = sp_max_p[b], sn = sp_min_p[b];
    float spma = (ca > sx || ca < sn) ? NEGINF : tba;
    float spsa = sp_logit[b * 64 + ca] + spma;
    SR1 rsp;
    sampleLo(g_sp + spsa, spsa, spma, lane, rsp);

    // ---------------- tile2 sampling ----------------
    int t2min = rsp.a;
    int mt = (int)max_temporal[b];            // f32->s32 truncation (astype)
    int t2x = min(tile2_max[b], t2min + mt);  // <= 40
    float t2ma = (ca > t2x || ca < t2min) ? NEGINF : tba;
    float t2sa = tile_logits[b * 256 + ca] + t2ma;
    SR1 rt2;
    if (t2x >= 32) {                          // warp-uniform path (~15% rows)
        float tbb = tile_masks[base_tm + cb];
        float t2mb = (cb > t2x) ? NEGINF : tbb;   // cb >= 32 > t2min always
        float t2sb = tile_logits[b * 256 + cb] + t2mb;
        unsigned hidx = b64 + 32u + ((lane < 10) ? (unsigned)lane : 0u);
        float ghi = jax_gumbel(tf_bits(keys.k[4], keys.k[5], hidx));
        float vb = (lane < 10) ? (ghi + t2sb) : NEGINF;
        sampleHiLo(g_t2a + t2sa, vb, t2sa, t2sb, t2ma, t2mb, lane, rt2);
    } else {
        sampleLo(g_t2a + t2sa, t2sa, t2ma, lane, rt2);
    }

    // ---------------- p = 1..3 chained samplings ----------------
    float rbs = remain[b];
    int pa = rt2.a;
    int tact[4];
    float lpv[6], lmv[6];
    tact[0] = pa;
    lpv[0] = ro.lp;  lmv[0] = ro.lpm;
    lpv[1] = rt2.lp; lmv[1] = rt2.lpm;
    lpv[5] = rsp.lp; lmv[5] = rsp.lpm;

    const float DL[3] = {1.584962500721156f, 2.321928094887362f,
                         2.807354922057604f};
    const float LN2 = 0.69314718055994530942f;
    const int POFF[3] = {0, 13, 22};

#pragma unroll
    for (int p = 1; p <= 3; ++p) {
        // PRIMES[p-1]^pa: base 2 via exp2f (exact at ints, same as powf(2,·))
        if (p == 1)      rbs = rbs / exp2f((float)pa);
        else if (p == 2) rbs = rbs / powf(3.0f, (float)pa);
        else             rbs = rbs / powf(5.0f, (float)pa);
        float tf = (logf(fmaxf(rbs, 1.0f)) / LN2) / DL[p - 1];   // jnp.log2
        int tm = min(min(max((int)tf, 0), 63), budgets[b * 28 + li * 4 + p]);
        // tm <= 12 / 8 / 7 for p = 1 / 2 / 3 (rbs <= 1e6)
        float bma = tile_masks[base_tm + p * 64 + ca];
        float mka = (ca > tm) ? NEGINF : bma;
        float sca = tile_logits[b * 256 + p * 64 + ca] + mka;
        float gp = (p == 1) ? g_pack
                            : __shfl_sync(FULL, g_pack, (lane + POFF[p - 1]) & 31);
        SR1 rp;
        sampleLo(gp + sca, sca, mka, lane, rp);
        pa = rp.a;
        tact[p] = pa;
        lpv[1 + p] = rp.lp;
        lmv[1 + p] = rp.lpm;
    }

    // ---------------- outputs (vectorized, lane 0) ----------------
    if (lane == 0) {
        out[b] = (float)ro.a;
        float4* ta = (float4*)(out + B);           // 16B aligned: b*16 bytes
        float4* sa = (float4*)(out + 5 * B);
        ta[b] = make_float4((float)tact[0], (float)tact[1],
                            (float)tact[2], (float)tact[3]);
        sa[b] = make_float4((float)rsp.a, 0.0f, 0.0f, 0.0f);
        float2* lp = (float2*)(out + 9 * B + b * 6);    // 8B aligned
        float2* lm = (float2*)(out + 15 * B + b * 6);
        lp[0] = make_float2(lpv[0], lpv[1]);
        lp[1] = make_float2(lpv[2], lpv[3]);
        lp[2] = make_float2(lpv[4], lpv[5]);
        lm[0] = make_float2(lmv[0], lmv[1]);
        lm[1] = make_float2(lmv[2], lmv[3]);
        lm[2] = make_float2(lmv[4], lmv[5]);
    }
}

// ---------------- host: threefry for key split ----------------
static void tf_host(unsigned k0, unsigned k1, unsigned x0, unsigned x1,
                    unsigned* o0, unsigned* o1)
{
    unsigned ks2 = k0 ^ k1 ^ 0x1BD11BDAu;
    x0 += k0; x1 += k1;
#define HR(r) { x0 += x1; x1 = (x1 << (r)) | (x1 >> (32 - (r))); x1 ^= x0; }
    HR(13) HR(15) HR(26) HR(6)
    x0 += k1;  x1 += ks2 + 1u;
    HR(17) HR(29) HR(16) HR(24)
    x0 += ks2; x1 += k0 + 2u;
    HR(13) HR(15) HR(26) HR(6)
    x0 += k0;  x1 += k1 + 3u;
    HR(17) HR(29) HR(16) HR(24)
    x0 += k1;  x1 += ks2 + 4u;
    HR(13) HR(15) HR(26) HR(6)
    x0 += ks2; x1 += k0 + 5u;
#undef HR
    *o0 = x0; *o1 = x1;
}

extern "C" void kernel_launch(void* const* d_in, const int* in_sizes, int n_in,
                              void* d_out, int out_size)
{
    const float* order_mask = (const float*)d_in[1];
    const int*   budgets    = (const int*)d_in[2];
    const float* tile_masks = (const float*)d_in[3];
    const int*   d_loop     = 0;
    int base = 4;
    if (n_in >= 14 && in_sizes[4] <= 1 && in_sizes[5] <= 1) {
        d_loop = (const int*)d_in[5];
        base = 6;
    }
    const float* remain       = (const float*)d_in[base + 0];
    const int*   tile2_max    = (const int*)d_in[base + 1];
    const float* max_temporal = (const float*)d_in[base + 2];
    const int*   sp_max       = (const int*)d_in[base + 3];
    const int*   sp_min       = (const int*)d_in[base + 4];
    const float* order_logit  = (const float*)d_in[base + 5];
    const float* tile_logits  = (const float*)d_in[base + 6];
    const float* sp_logit     = (const float*)d_in[base + 7];

    int B = in_sizes[1] / 7;

    // jax.random.split(key(1), 6) partitionable: key_j = threefry((0,1),(0,j))
    Keys6 keys;
    for (int j = 0; j < 6; j++) {
        unsigned o0, o1;
        tf_host(0u, 1u, 0u, (unsigned)j, &o0, &o1);
        keys.k[2 * j] = o0;
        keys.k[2 * j + 1] = o1;
    }

    int threads = 256;
    int total = B * 32;
    int blocks = (total + threads - 1) / threads;
    pt_kernel<<<blocks, threads>>>(B, order_mask, budgets, tile_masks, remain,
                                   tile2_max, max_temporal, sp_max, sp_min,
                                   order_logit, tile_logits, sp_logit,
                                   d_loop, 2, (float*)d_out, keys);
    (void)out_size;
}

// round 15
// speedup vs baseline: 1.5385x; 1.5385x over previous
#include <cuda_runtime.h>
#include <math.h>

// ============================================================================
// ProgramTransformer sampling — JAX threefry PARTITIONABLE mode.
// One warp per batch row. Hoisted/packed RNG (4 warp threefrys + conditional
// t2-hi). Reductions via redux.sync + ballot; softmax z-path uses fast-math
// (__expf/__logf) since it cannot affect argmax actions; gumbel logf stays
// full precision (bit-matches XLA, decides actions).
// ============================================================================

struct Keys6 { unsigned k[12]; };

// ---------------- threefry2x32 (JAX schedule, 20 rounds) ----------------
__device__ __forceinline__ void tf2x32(unsigned k0, unsigned k1,
                                       unsigned x0, unsigned x1,
                                       unsigned &o0, unsigned &o1)
{
    unsigned ks2 = k0 ^ k1 ^ 0x1BD11BDAu;
    x0 += k0; x1 += k1;
#define TFR(r) { x0 += x1; x1 = __funnelshift_l(x1, x1, (r)); x1 ^= x0; }
    TFR(13) TFR(15) TFR(26) TFR(6)
    x0 += k1;  x1 += ks2 + 1u;
    TFR(17) TFR(29) TFR(16) TFR(24)
    x0 += ks2; x1 += k0 + 2u;
    TFR(13) TFR(15) TFR(26) TFR(6)
    x0 += k0;  x1 += k1 + 3u;
    TFR(17) TFR(29) TFR(16) TFR(24)
    x0 += k1;  x1 += ks2 + 4u;
    TFR(13) TFR(15) TFR(26) TFR(6)
    x0 += ks2; x1 += k0 + 5u;
#undef TFR
    o0 = x0; o1 = x1;
}

// partitionable 32-bit random bits for flat element idx
__device__ __forceinline__ unsigned tf_bits(unsigned k0, unsigned k1, unsigned idx)
{
    unsigned o0, o1;
    tf2x32(k0, k1, 0u, idx, o0, o1);
    return o0 ^ o1;
}

// jax uniform(minval=tiny,maxval=1) -> gumbel (full-precision: decides argmax)
__device__ __forceinline__ float jax_gumbel(unsigned bits)
{
    const float tiny = 1.17549435082228751e-38f;
    float f = __uint_as_float((bits >> 9) | 0x3f800000u) - 1.0f;
    float u = fmaxf(tiny, f + tiny);
    return -logf(-logf(u));
}

// float -> order-preserving unsigned (and back)
__device__ __forceinline__ unsigned f2o(float f)
{
    unsigned b = __float_as_uint(f);
    return (b & 0x80000000u) ? ~b : (b | 0x80000000u);
}
__device__ __forceinline__ float o2f(unsigned u)
{
    return __uint_as_float((u & 0x80000000u) ? (u ^ 0x80000000u) : ~u);
}

struct SR1 { int a; float lp, lpm; };

// ---------------- single-slot sampler (only cols 0..31 live) ----------------
__device__ __forceinline__ void sampleLo(float v, float s, float m, int lane, SR1 &r)
{
    const unsigned FULL = 0xFFFFFFFFu;
    // argmax with first-index tiebreak
    unsigned u = f2o(v);
    unsigned umax = __reduce_max_sync(FULL, u);
    int a = __reduce_min_sync(FULL, (u == umax) ? lane : 127);
    // score max + unmasked count
    float mx = o2f(__reduce_max_sync(FULL, f2o(s)));
    int cnt = __popc(__ballot_sync(FULL, m == 0.0f));
    // softmax denom (fast path — cannot flip actions, lp tol = 1e-3)
    float z = __expf(s - mx);               // s=-inf -> 0
#pragma unroll
    for (int o = 16; o; o >>= 1) z += __shfl_xor_sync(FULL, z, o);
    float sact = __shfl_sync(FULL, s, a);
    r.a = a;
    r.lp = sact - mx - __logf(z);
    r.lpm = (cnt > 1) ? 1.0f : 0.0f;
}

// ---------------- two-slot sampler (cols lane and lane+32) ----------------
__device__ __forceinline__ void sampleHiLo(float va, float vb,
                                           float sa, float sb,
                                           float ma, float mb, int lane, SR1 &r)
{
    const unsigned FULL = 0xFFFFFFFFu;
    float bv = va; int bi = lane;
    if (vb > bv) { bv = vb; bi = lane + 32; }   // tie -> keep smaller col
    unsigned u = f2o(bv);
    unsigned umax = __reduce_max_sync(FULL, u);
    int a = __reduce_min_sync(FULL, (u == umax) ? bi : 127);
    float mx = o2f(__reduce_max_sync(FULL, f2o(fmaxf(sa, sb))));
    int cnt = __popc(__ballot_sync(FULL, ma == 0.0f)) +
              __popc(__ballot_sync(FULL, mb == 0.0f));
    float z = __expf(sa - mx) + __expf(sb - mx);
#pragma unroll
    for (int o = 16; o; o >>= 1) z += __shfl_xor_sync(FULL, z, o);
    float ps = (a >= 32) ? sb : sa;
    float sact = __shfl_sync(FULL, ps, a & 31);
    r.a = a;
    r.lp = sact - mx - __logf(z);
    r.lpm = (cnt > 1) ? 1.0f : 0.0f;
}

// ============================================================================
__global__ void __launch_bounds__(256)
pt_kernel(int B,
          const float* __restrict__ order_mask,
          const int*   __restrict__ budgets,
          const float* __restrict__ tile_masks,
          const float* __restrict__ remain,
          const int*   __restrict__ tile2_max,
          const float* __restrict__ max_temporal,
          const int*   __restrict__ sp_max_p,
          const int*   __restrict__ sp_min_p,
          const float* __restrict__ order_logit,
          const float* __restrict__ tile_logits,
          const float* __restrict__ sp_logit,
          const int*   __restrict__ d_loop,
          int li_const,
          float* __restrict__ out,
          Keys6 keys)
{
    const unsigned FULL = 0xFFFFFFFFu;
    const float NEGINF = __int_as_float(0xff800000);
    int gt = blockIdx.x * blockDim.x + threadIdx.x;
    int b = gt >> 5;
    if (b >= B) return;
    int lane = gt & 31;
    int li = d_loop ? d_loop[0] : li_const;

    int ca = lane, cb = lane + 32;
    unsigned b64 = (unsigned)(b * 64);
    int base_tm = b * 1792 + li * 256;       // tile_masks (B,7,4,64)

    // ======== hoisted random bits (4 warp-wide threefry+gumbel) ========
    float g_ord  = jax_gumbel(tf_bits(keys.k[0], keys.k[1],
                                      (unsigned)(b * 7) + (unsigned)lane));
    float g_sp   = jax_gumbel(tf_bits(keys.k[2], keys.k[3], b64 + (unsigned)lane));
    float g_t2a  = jax_gumbel(tf_bits(keys.k[4], keys.k[5], b64 + (unsigned)lane));
    // packed p1/p2/p3 (keys 3/4/5): p1 cols0-12 lanes0-12, p2 cols0-8
    // lanes13-21, p3 cols0-7 lanes22-29; lanes 30-31 duplicate p3 col0.
    unsigned pk0, pk1, poff;
    if (lane < 13)      { pk0 = keys.k[6];  pk1 = keys.k[7];  poff = (unsigned)lane; }
    else if (lane < 22) { pk0 = keys.k[8];  pk1 = keys.k[9];  poff = (unsigned)(lane - 13); }
    else                { pk0 = keys.k[10]; pk1 = keys.k[11]; poff = (lane < 30) ? (unsigned)(lane - 22) : 0u; }
    float g_pack = jax_gumbel(tf_bits(pk0, pk1, b64 + poff));

    // ---------------- order sampling (C=7, keys[0]) ----------------
    float om = NEGINF, os = NEGINF;
    if (lane < 7) {
        om = order_mask[b * 7 + lane];
        os = order_logit[b * 7 + lane] + om;
    }
    SR1 ro;
    sampleLo(lane < 7 ? (g_ord + os) : NEGINF, os, om, lane, ro);

    // ---------------- sp sampling (upper half always masked) ----------------
    float tba = tile_masks[base_tm + ca];
    int sx = sp_max_p[b], sn = sp_min_p[b];
    float spma = (ca > sx || ca < sn) ? NEGINF : tba;
    float spsa = sp_logit[b * 64 + ca] + spma;
    SR1 rsp;
    sampleLo(g_sp + spsa, spsa, spma, lane, rsp);

    // ---------------- tile2 sampling ----------------
    int t2min = rsp.a;
    int mt = (int)max_temporal[b];            // f32->s32 truncation (astype)
    int t2x = min(tile2_max[b], t2min + mt);  // <= 40
    float t2ma = (ca > t2x || ca < t2min) ? NEGINF : tba;
    float t2sa = tile_logits[b * 256 + ca] + t2ma;
    SR1 rt2;
    if (t2x >= 32) {                          // warp-uniform path (~15% rows)
        float tbb = tile_masks[base_tm + cb];
        float t2mb = (cb > t2x) ? NEGINF : tbb;   // cb >= 32 > t2min always
        float t2sb = tile_logits[b * 256 + cb] + t2mb;
        unsigned hidx = b64 + 32u + ((lane < 10) ? (unsigned)lane : 0u);
        float ghi = jax_gumbel(tf_bits(keys.k[4], keys.k[5], hidx));
        float vb = (lane < 10) ? (ghi + t2sb) : NEGINF;
        sampleHiLo(g_t2a + t2sa, vb, t2sa, t2sb, t2ma, t2mb, lane, rt2);
    } else {
        sampleLo(g_t2a + t2sa, t2sa, t2ma, lane, rt2);
    }

    // ---------------- p = 1..3 chained samplings ----------------
    float rbs = remain[b];
    int pa = rt2.a;
    int tact[4];
    float lpv[6], lmv[6];
    tact[0] = pa;
    lpv[0] = ro.lp;  lmv[0] = ro.lpm;
    lpv[1] = rt2.lp; lmv[1] = rt2.lpm;
    lpv[5] = rsp.lp; lmv[5] = rsp.lpm;

    const float PB[3] = {2.0f, 3.0f, 5.0f};
    const float DL[3] = {1.584962500721156f, 2.321928094887362f,
                         2.807354922057604f};
    const float LN2 = 0.69314718055994530942f;
    const int POFF[3] = {0, 13, 22};

#pragma unroll
    for (int p = 1; p <= 3; ++p) {
        rbs = rbs / powf(PB[p - 1], (float)pa);
        float tf = (logf(fmaxf(rbs, 1.0f)) / LN2) / DL[p - 1];   // jnp.log2
        int tm = min(min(max((int)tf, 0), 63), budgets[b * 28 + li * 4 + p]);
        // tm <= 12 / 8 / 7 for p = 1 / 2 / 3 (rbs <= 1e6)
        float bma = tile_masks[base_tm + p * 64 + ca];
        float mka = (ca > tm) ? NEGINF : bma;
        float sca = tile_logits[b * 256 + p * 64 + ca] + mka;
        float gp = (p == 1) ? g_pack
                            : __shfl_sync(FULL, g_pack, (lane + POFF[p - 1]) & 31);
        SR1 rp;
        sampleLo(gp + sca, sca, mka, lane, rp);
        pa = rp.a;
        tact[p] = pa;
        lpv[1 + p] = rp.lp;
        lmv[1 + p] = rp.lpm;
    }

    // ---------------- outputs (all f32, concatenated) ----------------
    if (lane == 0) {
        out[b] = (float)ro.a;
        float* ta = out + B;
        float* sa = out + 5 * B;
        float* lp = out + 9 * B;
        float* lm = out + 15 * B;
#pragma unroll
        for (int i = 0; i < 4; i++) ta[b * 4 + i] = (float)tact[i];
        sa[b * 4 + 0] = (float)rsp.a;
        sa[b * 4 + 1] = 0.0f; sa[b * 4 + 2] = 0.0f; sa[b * 4 + 3] = 0.0f;
#pragma unroll
        for (int i = 0; i < 6; i++) {
            lp[b * 6 + i] = lpv[i];
            lm[b * 6 + i] = lmv[i];
        }
    }
}

// ---------------- host: threefry for key split ----------------
static void tf_host(unsigned k0, unsigned k1, unsigned x0, unsigned x1,
                    unsigned* o0, unsigned* o1)
{
    unsigned ks2 = k0 ^ k1 ^ 0x1BD11BDAu;
    x0 += k0; x1 += k1;
#define HR(r) { x0 += x1; x1 = (x1 << (r)) | (x1 >> (32 - (r))); x1 ^= x0; }
    HR(13) HR(15) HR(26) HR(6)
    x0 += k1;  x1 += ks2 + 1u;
    HR(17) HR(29) HR(16) HR(24)
    x0 += ks2; x1 += k0 + 2u;
    HR(13) HR(15) HR(26) HR(6)
    x0 += k0;  x1 += k1 + 3u;
    HR(17) HR(29) HR(16) HR(24)
    x0 += k1;  x1 += ks2 + 4u;
    HR(13) HR(15) HR(26) HR(6)
    x0 += ks2; x1 += k0 + 5u;
#undef HR
    *o0 = x0; *o1 = x1;
}

extern "C" void kernel_launch(void* const* d_in, const int* in_sizes, int n_in,
                              void* d_out, int out_size)
{
    const float* order_mask = (const float*)d_in[1];
    const int*   budgets    = (const int*)d_in[2];
    const float* tile_masks = (const float*)d_in[3];
    const int*   d_loop     = 0;
    int base = 4;
    if (n_in >= 14 && in_sizes[4] <= 1 && in_sizes[5] <= 1) {
        d_loop = (const int*)d_in[5];
        base = 6;
    }
    const float* remain       = (const float*)d_in[base + 0];
    const int*   tile2_max    = (const int*)d_in[base + 1];
    const float* max_temporal = (const float*)d_in[base + 2];
    const int*   sp_max       = (const int*)d_in[base + 3];
    const int*   sp_min       = (const int*)d_in[base + 4];
    const float* order_logit  = (const float*)d_in[base + 5];
    const float* tile_logits  = (const float*)d_in[base + 6];
    const float* sp_logit     = (const float*)d_in[base + 7];

    int B = in_sizes[1] / 7;

    // jax.random.split(key(1), 6) partitionable: key_j = threefry((0,1),(0,j))
    Keys6 keys;
    for (int j = 0; j < 6; j++) {
        unsigned o0, o1;
        tf_host(0u, 1u, 0u, (unsigned)j, &o0, &o1);
        keys.k[2 * j] = o0;
        keys.k[2 * j + 1] = o1;
    }

    int threads = 256;
    int total = B * 32;
    int blocks = (total + threads - 1) / threads;
    pt_kernel<<<blocks, threads>>>(B, order_mask, budgets, tile_masks, remain,
                                   tile2_max, max_temporal, sp_max, sp_min,
                                   order_logit, tile_logits, sp_logit,
                                   d_loop, 2, (float*)d_out, keys);
    (void)out_size;
}

// round 17
// speedup vs baseline: 1.8132x; 1.1786x over previous
#include <cuda_runtime.h>
#include <math.h>

// ============================================================================
// ProgramTransformer sampling — JAX threefry PARTITIONABLE mode.
// One warp per batch row. Hoisted/packed RNG (4 warp threefrys + conditional
// t2-hi). redux.sync reductions + butterfly z-sum; fast-math softmax path.
// NEW: p-loop rbs chain in LOG DOMAIN — one logf(remain) upfront, then
// FMA/FMAX/FMUL per stage instead of powf+logf+fdiv (saves ~200 slots/warp).
// Gumbel logf stays full precision (decides actions, bit-matches XLA).
// ============================================================================

struct Keys6 { unsigned k[12]; };

// ---------------- threefry2x32 (JAX schedule, 20 rounds) ----------------
__device__ __forceinline__ void tf2x32(unsigned k0, unsigned k1,
                                       unsigned x0, unsigned x1,
                                       unsigned &o0, unsigned &o1)
{
    unsigned ks2 = k0 ^ k1 ^ 0x1BD11BDAu;
    x0 += k0; x1 += k1;
#define TFR(r) { x0 += x1; x1 = __funnelshift_l(x1, x1, (r)); x1 ^= x0; }
    TFR(13) TFR(15) TFR(26) TFR(6)
    x0 += k1;  x1 += ks2 + 1u;
    TFR(17) TFR(29) TFR(16) TFR(24)
    x0 += ks2; x1 += k0 + 2u;
    TFR(13) TFR(15) TFR(26) TFR(6)
    x0 += k0;  x1 += k1 + 3u;
    TFR(17) TFR(29) TFR(16) TFR(24)
    x0 += k1;  x1 += ks2 + 4u;
    TFR(13) TFR(15) TFR(26) TFR(6)
    x0 += ks2; x1 += k0 + 5u;
#undef TFR
    o0 = x0; o1 = x1;
}

// partitionable 32-bit random bits for flat element idx
__device__ __forceinline__ unsigned tf_bits(unsigned k0, unsigned k1, unsigned idx)
{
    unsigned o0, o1;
    tf2x32(k0, k1, 0u, idx, o0, o1);
    return o0 ^ o1;
}

// jax uniform(minval=tiny,maxval=1) -> gumbel (full-precision: decides argmax)
__device__ __forceinline__ float jax_gumbel(unsigned bits)
{
    const float tiny = 1.17549435082228751e-38f;
    float f = __uint_as_float((bits >> 9) | 0x3f800000u) - 1.0f;
    float u = fmaxf(tiny, f + tiny);
    return -logf(-logf(u));
}

// float -> order-preserving unsigned (and back)
__device__ __forceinline__ unsigned f2o(float f)
{
    unsigned b = __float_as_uint(f);
    return (b & 0x80000000u) ? ~b : (b | 0x80000000u);
}
__device__ __forceinline__ float o2f(unsigned u)
{
    return __uint_as_float((u & 0x80000000u) ? (u ^ 0x80000000u) : ~u);
}

struct SR1 { int a; float lp, lpm; };

// ---------------- single-slot sampler (only cols 0..31 live) ----------------
__device__ __forceinline__ void sampleLo(float v, float s, float m, int lane, SR1 &r)
{
    const unsigned FULL = 0xFFFFFFFFu;
    // argmax with first-index tiebreak
    unsigned u = f2o(v);
    unsigned umax = __reduce_max_sync(FULL, u);
    int a = __reduce_min_sync(FULL, (u == umax) ? lane : 127);
    // score max + unmasked count
    float mx = o2f(__reduce_max_sync(FULL, f2o(s)));
    int cnt = __popc(__ballot_sync(FULL, m == 0.0f));
    // softmax denom (fast path — cannot flip actions, lp tol = 1e-3)
    float z = __expf(s - mx);               // s=-inf -> 0
#pragma unroll
    for (int o = 16; o; o >>= 1) z += __shfl_xor_sync(FULL, z, o);
    float sact = __shfl_sync(FULL, s, a);
    r.a = a;
    r.lp = sact - mx - __logf(z);
    r.lpm = (cnt > 1) ? 1.0f : 0.0f;
}

// ---------------- two-slot sampler (cols lane and lane+32) ----------------
__device__ __forceinline__ void sampleHiLo(float va, float vb,
                                           float sa, float sb,
                                           float ma, float mb, int lane, SR1 &r)
{
    const unsigned FULL = 0xFFFFFFFFu;
    float bv = va; int bi = lane;
    if (vb > bv) { bv = vb; bi = lane + 32; }   // tie -> keep smaller col
    unsigned u = f2o(bv);
    unsigned umax = __reduce_max_sync(FULL, u);
    int a = __reduce_min_sync(FULL, (u == umax) ? bi : 127);
    float mx = o2f(__reduce_max_sync(FULL, f2o(fmaxf(sa, sb))));
    int cnt = __popc(__ballot_sync(FULL, ma == 0.0f)) +
              __popc(__ballot_sync(FULL, mb == 0.0f));
    float z = __expf(sa - mx) + __expf(sb - mx);
#pragma unroll
    for (int o = 16; o; o >>= 1) z += __shfl_xor_sync(FULL, z, o);
    float ps = (a >= 32) ? sb : sa;
    float sact = __shfl_sync(FULL, ps, a & 31);
    r.a = a;
    r.lp = sact - mx - __logf(z);
    r.lpm = (cnt > 1) ? 1.0f : 0.0f;
}

// ============================================================================
__global__ void __launch_bounds__(256)
pt_kernel(int B,
          const float* __restrict__ order_mask,
          const int*   __restrict__ budgets,
          const float* __restrict__ tile_masks,
          const float* __restrict__ remain,
          const int*   __restrict__ tile2_max,
          const float* __restrict__ max_temporal,
          const int*   __restrict__ sp_max_p,
          const int*   __restrict__ sp_min_p,
          const float* __restrict__ order_logit,
          const float* __restrict__ tile_logits,
          const float* __restrict__ sp_logit,
          const int*   __restrict__ d_loop,
          int li_const,
          float* __restrict__ out,
          Keys6 keys)
{
    const unsigned FULL = 0xFFFFFFFFu;
    const float NEGINF = __int_as_float(0xff800000);
    int gt = blockIdx.x * blockDim.x + threadIdx.x;
    int b = gt >> 5;
    if (b >= B) return;
    int lane = gt & 31;
    int li = d_loop ? d_loop[0] : li_const;

    int ca = lane, cb = lane + 32;
    unsigned b64 = (unsigned)(b * 64);
    int base_tm = b * 1792 + li * 256;       // tile_masks (B,7,4,64)

    // ======== hoisted random bits (4 warp-wide threefry+gumbel) ========
    float g_ord  = jax_gumbel(tf_bits(keys.k[0], keys.k[1],
                                      (unsigned)(b * 7) + (unsigned)lane));
    float g_sp   = jax_gumbel(tf_bits(keys.k[2], keys.k[3], b64 + (unsigned)lane));
    float g_t2a  = jax_gumbel(tf_bits(keys.k[4], keys.k[5], b64 + (unsigned)lane));
    // packed p1/p2/p3 (keys 3/4/5): p1 cols0-12 lanes0-12, p2 cols0-8
    // lanes13-21, p3 cols0-7 lanes22-29; lanes 30-31 duplicate p3 col0.
    unsigned pk0, pk1, poff;
    if (lane < 13)      { pk0 = keys.k[6];  pk1 = keys.k[7];  poff = (unsigned)lane; }
    else if (lane < 22) { pk0 = keys.k[8];  pk1 = keys.k[9];  poff = (unsigned)(lane - 13); }
    else                { pk0 = keys.k[10]; pk1 = keys.k[11]; poff = (lane < 30) ? (unsigned)(lane - 22) : 0u; }
    float g_pack = jax_gumbel(tf_bits(pk0, pk1, b64 + poff));

    // ---------------- order sampling (C=7, keys[0]) ----------------
    float om = NEGINF, os = NEGINF;
    if (lane < 7) {
        om = order_mask[b * 7 + lane];
        os = order_logit[b * 7 + lane] + om;
    }
    SR1 ro;
    sampleLo(lane < 7 ? (g_ord + os) : NEGINF, os, om, lane, ro);

    // ---------------- sp sampling (upper half always masked) ----------------
    float tba = tile_masks[base_tm + ca];
    int sx = sp_max_p[b], sn = sp_min_p[b];
    float spma = (ca > sx || ca < sn) ? NEGINF : tba;
    float spsa = sp_logit[b * 64 + ca] + spma;
    SR1 rsp;
    sampleLo(g_sp + spsa, spsa, spma, lane, rsp);

    // ---------------- tile2 sampling ----------------
    int t2min = rsp.a;
    int mt = (int)max_temporal[b];            // f32->s32 truncation (astype)
    int t2x = min(tile2_max[b], t2min + mt);  // <= 40
    float t2ma = (ca > t2x || ca < t2min) ? NEGINF : tba;
    float t2sa = tile_logits[b * 256 + ca] + t2ma;
    SR1 rt2;
    if (t2x >= 32) {                          // warp-uniform path (~15% rows)
        float tbb = tile_masks[base_tm + cb];
        float t2mb = (cb > t2x) ? NEGINF : tbb;   // cb >= 32 > t2min always
        float t2sb = tile_logits[b * 256 + cb] + t2mb;
        unsigned hidx = b64 + 32u + ((lane < 10) ? (unsigned)lane : 0u);
        float ghi = jax_gumbel(tf_bits(keys.k[4], keys.k[5], hidx));
        float vb = (lane < 10) ? (ghi + t2sb) : NEGINF;
        sampleHiLo(g_t2a + t2sa, vb, t2sa, t2sb, t2ma, t2mb, lane, rt2);
    } else {
        sampleLo(g_t2a + t2sa, t2sa, t2ma, lane, rt2);
    }

    // ---------------- p = 1..3 chained samplings (LOG-DOMAIN rbs) ----------
    // tf_p = ln(clip(rbs,1)) / ln(prime_p) with ln(rbs) tracked additively:
    // ln -= pa * ln(PRIMES[p-1]).  Matches the divide-then-log reference to
    // ~1e-6 in ln-space; tmax is an int floor usually clamped by budgets, so
    // action flips are vanishingly rare.
    float lnr = logf(remain[b]);
    int pa = rt2.a;
    int tact[4];
    float lpv[6], lmv[6];
    tact[0] = pa;
    lpv[0] = ro.lp;  lmv[0] = ro.lpm;
    lpv[1] = rt2.lp; lmv[1] = rt2.lpm;
    lpv[5] = rsp.lp; lmv[5] = rsp.lpm;

    const float LNP[3] = {0.69314718055994531f,     // ln 2
                          1.09861228866810969f,     // ln 3
                          1.60943791243410037f};    // ln 5
    const float INVL[3] = {0.91023922662683739f,    // 1/ln 3
                           0.62133493455961189f,    // 1/ln 5
                           0.51389834236975075f};   // 1/ln 7
    const int POFF[3] = {0, 13, 22};

#pragma unroll
    for (int p = 1; p <= 3; ++p) {
        lnr = fmaf(-(float)pa, LNP[p - 1], lnr);
        float tf = fmaxf(lnr, 0.0f) * INVL[p - 1];
        int tm = min(min(max((int)tf, 0), 63), budgets[b * 28 + li * 4 + p]);
        // tm <= 12 / 8 / 7 for p = 1 / 2 / 3 (rbs <= 1e6)
        float bma = tile_masks[base_tm + p * 64 + ca];
        float mka = (ca > tm) ? NEGINF : bma;
        float sca = tile_logits[b * 256 + p * 64 + ca] + mka;
        float gp = (p == 1) ? g_pack
                            : __shfl_sync(FULL, g_pack, (lane + POFF[p - 1]) & 31);
        SR1 rp;
        sampleLo(gp + sca, sca, mka, lane, rp);
        pa = rp.a;
        tact[p] = pa;
        lpv[1 + p] = rp.lp;
        lmv[1 + p] = rp.lpm;
    }

    // ---------------- outputs (all f32, concatenated) ----------------
    if (lane == 0) {
        out[b] = (float)ro.a;
        float* ta = out + B;
        float* sa = out + 5 * B;
        float* lp = out + 9 * B;
        float* lm = out + 15 * B;
#pragma unroll
        for (int i = 0; i < 4; i++) ta[b * 4 + i] = (float)tact[i];
        sa[b * 4 + 0] = (float)rsp.a;
        sa[b * 4 + 1] = 0.0f; sa[b * 4 + 2] = 0.0f; sa[b * 4 + 3] = 0.0f;
#pragma unroll
        for (int i = 0; i < 6; i++) {
            lp[b * 6 + i] = lpv[i];
            lm[b * 6 + i] = lmv[i];
        }
    }
}

// ---------------- host: threefry for key split ----------------
static void tf_host(unsigned k0, unsigned k1, unsigned x0, unsigned x1,
                    unsigned* o0, unsigned* o1)
{
    unsigned ks2 = k0 ^ k1 ^ 0x1BD11BDAu;
    x0 += k0; x1 += k1;
#define HR(r) { x0 += x1; x1 = (x1 << (r)) | (x1 >> (32 - (r))); x1 ^= x0; }
    HR(13) HR(15) HR(26) HR(6)
    x0 += k1;  x1 += ks2 + 1u;
    HR(17) HR(29) HR(16) HR(24)
    x0 += ks2; x1 += k0 + 2u;
    HR(13) HR(15) HR(26) HR(6)
    x0 += k0;  x1 += k1 + 3u;
    HR(17) HR(29) HR(16) HR(24)
    x0 += k1;  x1 += ks2 + 4u;
    HR(13) HR(15) HR(26) HR(6)
    x0 += ks2; x1 += k0 + 5u;
#undef HR
    *o0 = x0; *o1 = x1;
}

extern "C" void kernel_launch(void* const* d_in, const int* in_sizes, int n_in,
                              void* d_out, int out_size)
{
    const float* order_mask = (const float*)d_in[1];
    const int*   budgets    = (const int*)d_in[2];
    const float* tile_masks = (const float*)d_in[3];
    const int*   d_loop     = 0;
    int base = 4;
    if (n_in >= 14 && in_sizes[4] <= 1 && in_sizes[5] <= 1) {
        d_loop = (const int*)d_in[5];
        base = 6;
    }
    const float* remain       = (const float*)d_in[base + 0];
    const int*   tile2_max    = (const int*)d_in[base + 1];
    const float* max_temporal = (const float*)d_in[base + 2];
    const int*   sp_max       = (const int*)d_in[base + 3];
    const int*   sp_min       = (const int*)d_in[base + 4];
    const float* order_logit  = (const float*)d_in[base + 5];
    const float* tile_logits  = (const float*)d_in[base + 6];
    const float* sp_logit     = (const float*)d_in[base + 7];

    int B = in_sizes[1] / 7;

    // jax.random.split(key(1), 6) partitionable: key_j = threefry((0,1),(0,j))
    Keys6 keys;
    for (int j = 0; j < 6; j++) {
        unsigned o0, o1;
        tf_host(0u, 1u, 0u, (unsigned)j, &o0, &o1);
        keys.k[2 * j] = o0;
        keys.k[2 * j + 1] = o1;
    }

    int threads = 256;
    int total = B * 32;
    int blocks = (total + threads - 1) / threads;
    pt_kernel<<<blocks, threads>>>(B, order_mask, budgets, tile_masks, remain,
                                   tile2_max, max_temporal, sp_max, sp_min,
                                   order_logit, tile_logits, sp_logit,
                                   d_loop, 2, (float*)d_out, keys);
    (void)out_size;
}